// round 6
// baseline (speedup 1.0000x reference)
#include <cuda_runtime.h>

#define T_STEPS 512

// ---- packed f32x2 helpers (sm_100+ PTX) ----
__device__ __forceinline__ unsigned long long pack2(float lo, float hi){
    unsigned long long r;
    asm("mov.b64 %0, {%1, %2};" : "=l"(r) : "f"(lo), "f"(hi));
    return r;
}
__device__ __forceinline__ void ffma2(unsigned long long& acc, unsigned long long a, unsigned long long b){
    asm("fma.rn.f32x2 %0, %1, %2, %0;" : "+l"(acc) : "l"(a), "l"(b));
}
__device__ __forceinline__ float2 unpack2(unsigned long long v){
    float2 f;
    asm("mov.b64 {%0, %1}, %2;" : "=f"(f.x), "=f"(f.y) : "l"(v));
    return f;
}
__device__ __forceinline__ float fast_exp2(float x){
    float r; asm("ex2.approx.f32 %0, %1;" : "=f"(r) : "f"(x)); return r;
}
__device__ __forceinline__ float fast_rcp(float x){
    float r; asm("rcp.approx.f32 %0, %1;" : "=f"(r) : "f"(x)); return r;
}
__device__ __forceinline__ float sigmoidf_(float x){
    return fast_rcp(1.0f + fast_exp2(-1.4426950408889634f * x));
}
__device__ __forceinline__ float tanhf_(float x){
    float e = fast_exp2(-2.8853900817779268f * x);
    return fmaf(2.0f, fast_rcp(1.0f + e), -1.0f);
}

// ONE batch per warp, one warp per block, grid = B = 2048.
// Register-lean (<=170, launch_bounds 32x12) so 12 blocks/SM are resident:
// 3 warps/SMSP hide each other's serial tails (LDS latency, MUFU activation
// chain, syncwarp), unlike the grid-limited 1.75 warps/SMSP of the 2-batch
// variant. No block barriers anywhere in the recurrence (k-split lesson).
// Lane j owns hidden unit j (gate rows j, 32+j, 64+j, 96+j).
// h history staged in a warp-private smem slab hs[32 steps][36 floats]:
//   - 36-float row stride keeps every row 16B-aligned -> LDS.128 broadcast
//   - write row ts, read row ts-1 (natural double buffer)
//   - FC head deferred: once per 32 steps, transposed (lane j = step j),
//     coalesced STG, no per-step shfl butterfly.
__global__ void __launch_bounds__(32, 12) lstm_1b(
    const float* __restrict__ x,
    const float* __restrict__ W_ih,
    const float* __restrict__ W_hh,
    const float* __restrict__ b_ih,
    const float* __restrict__ b_hh,
    const float* __restrict__ W_fc,
    const float* __restrict__ b_fc,
    float* __restrict__ out,
    int B)
{
    const int lane = threadIdx.x;
    const int b = blockIdx.x;
    if (b >= B) return;

    __shared__ __align__(16) float hs[32][36];
    __shared__ float wfcs[32];

    // ---- preload weights into registers (amortized over 512 steps) ----
    unsigned long long w2[4][16];   // 4 gate rows x 16 packed k-pairs = 128 regs
    float wxa[4], wxb[4], bias[4];  // scalar x-projection weights + fused bias
#pragma unroll
    for (int r = 0; r < 4; r++){
        const int row = r * 32 + lane;
        const float4* wr = reinterpret_cast<const float4*>(W_hh) + row * 8;
#pragma unroll
        for (int q = 0; q < 8; q++){
            float4 v = wr[q];
            w2[r][2*q]   = pack2(v.x, v.y);
            w2[r][2*q+1] = pack2(v.z, v.w);
        }
        wxa[r]  = W_ih[row*2 + 0];
        wxb[r]  = W_ih[row*2 + 1];
        bias[r] = b_ih[row] + b_hh[row];
    }
    wfcs[lane] = W_fc[lane];
    const float bfc = b_fc[0];

    float c = 0.0f;
    hs[31][lane] = 0.0f;            // h_{-1} = 0 (read by step 0)
    __syncwarp();

    const float2* xrow = reinterpret_cast<const float2*>(x) + (size_t)b * T_STEPS;

    for (int tb = 0; tb < T_STEPS / 32; tb++){
#pragma unroll 1
        for (int ts = 0; ts < 32; ts++){
            const float2 xv = xrow[(tb << 5) + ts];   // L1-resident after step 1

            const int rp = (ts + 31) & 31;            // row holding h_{t-1}
            const ulonglong2* hp = reinterpret_cast<const ulonglong2*>(&hs[rp][0]);

            // init accumulators: lo = bias + x0*wxa, hi = x1*wxb
            unsigned long long acc0 = pack2(fmaf(xv.x, wxa[0], bias[0]), xv.y * wxb[0]);
            unsigned long long acc1 = pack2(fmaf(xv.x, wxa[1], bias[1]), xv.y * wxb[1]);
            unsigned long long acc2 = pack2(fmaf(xv.x, wxa[2], bias[2]), xv.y * wxb[2]);
            unsigned long long acc3 = pack2(fmaf(xv.x, wxa[3], bias[3]), xv.y * wxb[3]);

            // 4x32 MAC core: 64 packed FFMA2, 4 independent chains,
            // h streamed from the broadcast row (8x LDS.128)
#pragma unroll
            for (int q = 0; q < 8; q++){
                ulonglong2 v = hp[q];
                ffma2(acc0, v.x, w2[0][2*q]);
                ffma2(acc1, v.x, w2[1][2*q]);
                ffma2(acc2, v.x, w2[2][2*q]);
                ffma2(acc3, v.x, w2[3][2*q]);
                ffma2(acc0, v.y, w2[0][2*q+1]);
                ffma2(acc1, v.y, w2[1][2*q+1]);
                ffma2(acc2, v.y, w2[2][2*q+1]);
                ffma2(acc3, v.y, w2[3][2*q+1]);
            }

            float2 a0 = unpack2(acc0);
            float2 a1 = unpack2(acc1);
            float2 a2 = unpack2(acc2);
            float2 a3 = unpack2(acc3);
            const float ig = sigmoidf_(a0.x + a0.y);
            const float fg = sigmoidf_(a1.x + a1.y);
            const float gg = tanhf_   (a2.x + a2.y);
            const float og = sigmoidf_(a3.x + a3.y);
            c = fmaf(fg, c, ig * gg);
            const float h = og * tanhf_(c);

            hs[ts][lane] = h;       // publish h_t for next step
            __syncwarp();
        }

        // ---- deferred FC head for this 32-step chunk ----
        // lane j computes out[t = tb*32 + j] = dot(h_t, wfc) + bfc
        // (hs[lane][k] is a 4-way bank conflict, ~128 cyc per 32 steps: noise)
        float p = 0.0f;
#pragma unroll
        for (int k = 0; k < 32; k++)
            p = fmaf(hs[lane][k], wfcs[k], p);
        out[(size_t)b * T_STEPS + (tb << 5) + lane] = p + bfc;
        __syncwarp();   // FC reads complete before next chunk overwrites rows
    }
}

extern "C" void kernel_launch(void* const* d_in, const int* in_sizes, int n_in,
                              void* d_out, int out_size)
{
    const float* x   = (const float*)d_in[0];
    const float* Wih = (const float*)d_in[1];
    const float* Whh = (const float*)d_in[2];
    const float* bih = (const float*)d_in[3];
    const float* bhh = (const float*)d_in[4];
    const float* Wfc = (const float*)d_in[5];
    const float* bfc = (const float*)d_in[6];
    float* out = (float*)d_out;

    const int B = out_size / T_STEPS;      // OUT=1 -> out_size = B*T
    lstm_1b<<<B, 32>>>(x, Wih, Whh, bih, bhh, Wfc, bfc, out, B);
}

// round 7
// speedup vs baseline: 1.4634x; 1.4634x over previous
#include <cuda_runtime.h>

#define T_STEPS 512

// ---- packed f32x2 helpers (sm_100+ PTX) ----
__device__ __forceinline__ unsigned long long pack2(float lo, float hi){
    unsigned long long r;
    asm("mov.b64 %0, {%1, %2};" : "=l"(r) : "f"(lo), "f"(hi));
    return r;
}
__device__ __forceinline__ void ffma2(unsigned long long& acc, unsigned long long a, unsigned long long b){
    asm("fma.rn.f32x2 %0, %1, %2, %0;" : "+l"(acc) : "l"(a), "l"(b));
}
__device__ __forceinline__ float2 unpack2(unsigned long long v){
    float2 f;
    asm("mov.b64 {%0, %1}, %2;" : "=f"(f.x), "=f"(f.y) : "l"(v));
    return f;
}
// HW tanh (MUFU, sm_75+): 1 op, ~16 cyc, max err ~2^-10.8 — replaces the
// 2xMUFU+3ALU precise chains. Sigmoid built on it: s(x)=0.5*tanh(x/2)+0.5.
__device__ __forceinline__ float tanh_a(float x){
    float r; asm("tanh.approx.f32 %0, %1;" : "=f"(r) : "f"(x)); return r;
}
__device__ __forceinline__ float sigmoid_a(float x){
    return fmaf(0.5f, tanh_a(0.5f * x), 0.5f);
}

// Architecture = R3 (best): TWO batch elements per warp, one warp per block,
// grid = B/2 = 1024 -> one wave. The two batches' dependency chains interleave
// inside one warp and hide each other's latency (beats every occupancy-raising
// variant tried: lean 1b/warp, k-split, high-occ 1b/warp).
// This round: activation critical path cut ~2x via hardware tanh.approx.
__global__ void __launch_bounds__(32, 8) lstm_fused2(
    const float* __restrict__ x,
    const float* __restrict__ W_ih,
    const float* __restrict__ W_hh,
    const float* __restrict__ b_ih,
    const float* __restrict__ b_hh,
    const float* __restrict__ W_fc,
    const float* __restrict__ b_fc,
    float* __restrict__ out,
    int B)
{
    const int lane = threadIdx.x;
    const int b0 = blockIdx.x * 2;
    const int b1 = b0 + 1;
    const bool has1 = (b1 < B);
    const int b1m = has1 ? b1 : b0;

    __shared__ __align__(16) float hs[2][32][36];
    __shared__ float wfcs[32];

    // ---- preload shared weights into registers (amortized over 512 steps) ----
    unsigned long long w2[4][16];   // 4 gate rows x 16 packed k-pairs = 128 regs
    unsigned long long wx2[4];
    float bias[4];
#pragma unroll
    for (int r = 0; r < 4; r++){
        const int row = r * 32 + lane;
        const float4* wr = reinterpret_cast<const float4*>(W_hh) + row * 8;
#pragma unroll
        for (int q = 0; q < 8; q++){
            float4 v = wr[q];
            w2[r][2*q]   = pack2(v.x, v.y);
            w2[r][2*q+1] = pack2(v.z, v.w);
        }
        wx2[r]  = pack2(W_ih[row*2 + 0], W_ih[row*2 + 1]);
        bias[r] = b_ih[row] + b_hh[row];
    }
    wfcs[lane] = W_fc[lane];
    const float bfc = b_fc[0];

    float c0 = 0.0f, c1 = 0.0f;
    hs[0][31][lane] = 0.0f;   // h_{-1} = 0 (read by step 0)
    hs[1][31][lane] = 0.0f;
    __syncwarp();

    const float2* xr0 = reinterpret_cast<const float2*>(x) + (size_t)b0  * T_STEPS;
    const float2* xr1 = reinterpret_cast<const float2*>(x) + (size_t)b1m * T_STEPS;
    float2 xv0 = xr0[0];
    float2 xv1 = xr1[0];

    for (int tb = 0; tb < T_STEPS / 32; tb++){
#pragma unroll 1
        for (int ts = 0; ts < 32; ts++){
            const int t = (tb << 5) + ts;
            const int tn = (t + 1 < T_STEPS) ? (t + 1) : t;
            float2 xn0 = xr0[tn];           // prefetch next inputs
            float2 xn1 = xr1[tn];

            const int rp = (ts + 31) & 31;  // row holding h_{t-1}
            const ulonglong2* hp0 = reinterpret_cast<const ulonglong2*>(&hs[0][rp][0]);
            const ulonglong2* hp1 = reinterpret_cast<const ulonglong2*>(&hs[1][rp][0]);

            // init accumulators: lo = bias + x0*w0, hi = x1*w1
            unsigned long long xp0 = pack2(xv0.x, xv0.y);
            unsigned long long xp1 = pack2(xv1.x, xv1.y);
            unsigned long long a00 = pack2(bias[0], 0.f), a01 = pack2(bias[1], 0.f);
            unsigned long long a02 = pack2(bias[2], 0.f), a03 = pack2(bias[3], 0.f);
            unsigned long long a10 = a00, a11 = a01, a12 = a02, a13 = a03;
            ffma2(a00, xp0, wx2[0]); ffma2(a01, xp0, wx2[1]);
            ffma2(a02, xp0, wx2[2]); ffma2(a03, xp0, wx2[3]);
            ffma2(a10, xp1, wx2[0]); ffma2(a11, xp1, wx2[1]);
            ffma2(a12, xp1, wx2[2]); ffma2(a13, xp1, wx2[3]);

            // MAC core: 128 packed FFMA2, 8 independent chains
#pragma unroll
            for (int q = 0; q < 8; q++){
                ulonglong2 v0 = hp0[q];
                ulonglong2 v1 = hp1[q];
                ffma2(a00, v0.x, w2[0][2*q]);   ffma2(a01, v0.x, w2[1][2*q]);
                ffma2(a02, v0.x, w2[2][2*q]);   ffma2(a03, v0.x, w2[3][2*q]);
                ffma2(a10, v1.x, w2[0][2*q]);   ffma2(a11, v1.x, w2[1][2*q]);
                ffma2(a12, v1.x, w2[2][2*q]);   ffma2(a13, v1.x, w2[3][2*q]);
                ffma2(a00, v0.y, w2[0][2*q+1]); ffma2(a01, v0.y, w2[1][2*q+1]);
                ffma2(a02, v0.y, w2[2][2*q+1]); ffma2(a03, v0.y, w2[3][2*q+1]);
                ffma2(a10, v1.y, w2[0][2*q+1]); ffma2(a11, v1.y, w2[1][2*q+1]);
                ffma2(a12, v1.y, w2[2][2*q+1]); ffma2(a13, v1.y, w2[3][2*q+1]);
            }

            // gates, batch 0 (hardware tanh path)
            {
                float2 f0 = unpack2(a00), f1 = unpack2(a01);
                float2 f2 = unpack2(a02), f3 = unpack2(a03);
                const float ig = sigmoid_a(f0.x + f0.y);
                const float fg = sigmoid_a(f1.x + f1.y);
                const float gg = tanh_a   (f2.x + f2.y);
                const float og = sigmoid_a(f3.x + f3.y);
                c0 = fmaf(fg, c0, ig * gg);
                hs[0][ts][lane] = og * tanh_a(c0);
            }
            // gates, batch 1
            {
                float2 f0 = unpack2(a10), f1 = unpack2(a11);
                float2 f2 = unpack2(a12), f3 = unpack2(a13);
                const float ig = sigmoid_a(f0.x + f0.y);
                const float fg = sigmoid_a(f1.x + f1.y);
                const float gg = tanh_a   (f2.x + f2.y);
                const float og = sigmoid_a(f3.x + f3.y);
                c1 = fmaf(fg, c1, ig * gg);
                hs[1][ts][lane] = og * tanh_a(c1);
            }

            __syncwarp();   // publish h_t before next step reads it
            xv0 = xn0;
            xv1 = xn1;
        }

        // ---- deferred FC head for this 32-step chunk ----
        // lane j computes out[t = tb*32 + j] = dot(h_t, wfc) + bfc
        float p0 = 0.0f, p1 = 0.0f;
#pragma unroll
        for (int k = 0; k < 32; k++){
            const float w = wfcs[k];
            p0 = fmaf(hs[0][lane][k], w, p0);
            p1 = fmaf(hs[1][lane][k], w, p1);
        }
        const int to = (tb << 5) + lane;
        out[(size_t)b0 * T_STEPS + to] = p0 + bfc;
        if (has1) out[(size_t)b1 * T_STEPS + to] = p1 + bfc;
        __syncwarp();   // chunk rows may be overwritten next chunk
    }
}

extern "C" void kernel_launch(void* const* d_in, const int* in_sizes, int n_in,
                              void* d_out, int out_size)
{
    const float* x   = (const float*)d_in[0];
    const float* Wih = (const float*)d_in[1];
    const float* Whh = (const float*)d_in[2];
    const float* bih = (const float*)d_in[3];
    const float* bhh = (const float*)d_in[4];
    const float* Wfc = (const float*)d_in[5];
    const float* bfc = (const float*)d_in[6];
    float* out = (float*)d_out;

    const int B = out_size / T_STEPS;      // OUT=1 -> out_size = B*T
    const int grid = (B + 1) / 2;          // two batch elements per warp
    lstm_fused2<<<grid, 32>>>(x, Wih, Whh, bih, bhh, Wfc, bfc, out, B);
}